// round 4
// baseline (speedup 1.0000x reference)
#include <cuda_runtime.h>
#include <cstdint>
#include <math.h>

#define B_ 512
#define N_ 128
#define F_ 128
#define K_ 4

#define FRAG_BYTES 33792   // 64 groups * 33 slots(pad) * 16B
#define WORDS_PER_CHUNK 2048

// ---------------- device scratch (allocation-free) ----------------
__device__ float g_bufA[(size_t)B_ * N_ * F_];
__device__ float g_bufB[(size_t)B_ * N_ * F_];
__device__ float g_D[B_ * N_];
__device__ float g_part[B_];
__device__ uint4 g_Ef[(size_t)B_ * 8 * WORDS_PER_CHUNK];   // A-frag packed D*E (tf32)
__device__ uint4 g_Gf[(size_t)B_ * 8 * WORDS_PER_CHUNK];   // B-frag packed G (tf32)
__device__ uint4 g_RWf[3 * 4 * 2 * WORDS_PER_CHUNK];       // A-frag packed RW (tf32)
__device__ uint4 g_SWf[3 * 2 * WORDS_PER_CHUNK];           // B-frag packed SW (tf32)

// ---------------- helpers ----------------
__device__ __forceinline__ uint32_t smem_u32(const void* p) {
    uint32_t a;
    asm("{ .reg .u64 t; cvta.to.shared.u64 t, %1; cvt.u32.u64 %0, t; }" : "=r"(a) : "l"(p));
    return a;
}
__device__ __forceinline__ uint32_t cvt_tf32(float x) {
    uint32_t u; asm("cvt.rna.tf32.f32 %0, %1;" : "=r"(u) : "f"(x)); return u;
}
__device__ __forceinline__ void sts32u(uint32_t a, uint32_t v) {
    asm volatile("st.shared.b32 [%0], %1;" :: "r"(a), "r"(v));
}
__device__ __forceinline__ void sts64u(uint32_t a, uint32_t v0, uint32_t v1) {
    asm volatile("st.shared.v2.b32 [%0], {%1,%2};" :: "r"(a), "r"(v0), "r"(v1));
}
__device__ __forceinline__ void lds128u(uint32_t* r, uint32_t a) {
    asm volatile("ld.shared.v4.b32 {%0,%1,%2,%3}, [%4];"
                 : "=r"(r[0]), "=r"(r[1]), "=r"(r[2]), "=r"(r[3]) : "r"(a));
}
__device__ __forceinline__ void cpasync16(uint32_t sa, const void* ga) {
    asm volatile("cp.async.cg.shared.global [%0], [%1], 16;" :: "r"(sa), "l"(ga));
}
#define CP_COMMIT() asm volatile("cp.async.commit_group;" ::: "memory")
#define CP_WAIT0()  asm volatile("cp.async.wait_group 0;" ::: "memory")

__device__ __forceinline__ void mma8(float* c, const uint32_t* a, uint32_t b0, uint32_t b1) {
    asm volatile(
        "mma.sync.aligned.m16n8k8.row.col.f32.tf32.tf32.f32 "
        "{%0,%1,%2,%3}, {%4,%5,%6,%7}, {%8,%9}, {%0,%1,%2,%3};"
        : "+f"(c[0]), "+f"(c[1]), "+f"(c[2]), "+f"(c[3])
        : "r"(a[0]), "r"(a[1]), "r"(a[2]), "r"(a[3]), "r"(b0), "r"(b1));
}

// A-fragment scatter (row i, k-indices kl0..kl0+3), rna-converted
__device__ __forceinline__ void stageA4(uint32_t buf, int i, int kl0, float4 v) {
    uint32_t u[4] = {cvt_tf32(v.x), cvt_tf32(v.y), cvt_tf32(v.z), cvt_tf32(v.w)};
    #pragma unroll
    for (int s = 0; s < 4; s++) {
        int kl = kl0 + s;
        int g = ((i >> 4) << 3) | (kl >> 3);
        int ln = ((i & 7) << 2) | (kl & 3);
        int rg = (((kl >> 2) & 1) << 1) | ((i >> 3) & 1);
        sts32u(buf + (uint32_t)(g * 33 + ln) * 16 + rg * 4, u[s]);
    }
}
// B-fragment scatter (col n, k-indices kl0..kl0+3)
__device__ __forceinline__ void stageB4(uint32_t buf, int n, int kl0, float4 v) {
    uint32_t u[4] = {cvt_tf32(v.x), cvt_tf32(v.y), cvt_tf32(v.z), cvt_tf32(v.w)};
    #pragma unroll
    for (int s = 0; s < 4; s++) {
        int kl = kl0 + s;
        int g = ((n >> 3) << 2) | (kl >> 4);
        int ln = ((n & 7) << 2) | (kl & 3);
        int rg = (kl >> 2) & 3;
        sts32u(buf + (uint32_t)(g * 33 + ln) * 16 + rg * 4, u[s]);
    }
}

// ---------------------------------------------------------------------------
// Degree norm
// ---------------------------------------------------------------------------
__global__ void deg_kernel(const float* __restrict__ E) {
    int warp = (blockIdx.x * blockDim.x + threadIdx.x) >> 5;
    int lane = threadIdx.x & 31;
    if (warp >= B_ * N_) return;
    const float* row = E + (size_t)warp * (N_ * K_);
    float s = 0.f;
    #pragma unroll 4
    for (int t = lane; t < N_ * K_; t += 32) s += row[t];
    #pragma unroll
    for (int o = 16; o > 0; o >>= 1) s += __shfl_xor_sync(0xffffffffu, s, o);
    if (lane == 0) g_D[warp] = 1.0f / (s + (float)K_);
}

// ---------------------------------------------------------------------------
// escale: Ef[b][kc][w] = A-frag packed tf32(D[i] * E[b][i][jk])  (once)
// ---------------------------------------------------------------------------
__global__ __launch_bounds__(256) void escale_kernel(const float* __restrict__ E) {
    __shared__ float Dsh[128];
    __shared__ float Es[128 * 68];     // row stride 68 (conflict-avoid)
    const int b = blockIdx.x, tid = threadIdx.x;
    if (tid < 128) Dsh[tid] = g_D[b * 128 + tid];
    const float4* E4 = (const float4*)(E + (size_t)b * 65536);
    uint4* Efb = g_Ef + (size_t)b * 8 * WORDS_PER_CHUNK;

    for (int kc = 0; kc < 8; kc++) {
        __syncthreads();
        for (int l = tid; l < 2048; l += 256) {
            int i = l >> 4, q4 = l & 15;
            float4 v = E4[(size_t)i * 128 + kc * 16 + q4];
            float d = Dsh[i];
            v.x *= d; v.y *= d; v.z *= d; v.w *= d;
            *(float4*)&Es[i * 68 + q4 * 4] = v;
        }
        __syncthreads();
        for (int w = tid; w < 2048; w += 256) {
            int g = w >> 5, ln = w & 31;
            int i0 = ((g >> 3) << 4) | (ln >> 2);
            int kl0 = ((g & 7) << 3) | (ln & 3);
            uint4 u;
            u.x = cvt_tf32(Es[i0 * 68 + kl0]);
            u.y = cvt_tf32(Es[(i0 + 8) * 68 + kl0]);
            u.z = cvt_tf32(Es[i0 * 68 + kl0 + 4]);
            u.w = cvt_tf32(Es[(i0 + 8) * 68 + kl0 + 4]);
            Efb[kc * WORDS_PER_CHUNK + w] = u;
        }
    }
}

// ---------------------------------------------------------------------------
// Prep: pack RW (A-frag) and SW (B-frag), once.
// ---------------------------------------------------------------------------
__global__ void prep_kernel(const float* __restrict__ RW1, const float* __restrict__ SW1,
                            const float* __restrict__ RW2, const float* __restrict__ SW2,
                            const float* __restrict__ RW3, const float* __restrict__ SW3)
{
    int bid = blockIdx.x, tid = threadIdx.x;
    const float* RWs[3] = {RW1, RW2, RW3};
    const float* SWs[3] = {SW1, SW2, SW3};
    if (bid < 24) {
        int l = bid >> 3, k = (bid >> 1) & 3, ch = bid & 1;
        const float* RW = RWs[l];
        uint4* dst = g_RWf + (size_t)(((l * 4 + k) * 2 + ch)) * WORDS_PER_CHUNK;
        for (int w = tid; w < 2048; w += 256) {
            int g = w >> 5, ln = w & 31;
            uint32_t u[4];
            #pragma unroll
            for (int rg = 0; rg < 4; rg++) {
                int n = ((g >> 3) << 4) | ((rg & 1) << 3) | (ln >> 2);
                int m = ch * 64 + (((g & 7) << 3) | (((rg >> 1) & 1) << 2) | (ln & 3));
                u[rg] = cvt_tf32(RW[(m * 128 + n) * 4 + k]);
            }
            dst[w] = make_uint4(u[0], u[1], u[2], u[3]);
        }
    } else {
        int b2 = bid - 24;
        int l = b2 >> 1, c = b2 & 1;
        const float* SW = SWs[l];
        uint4* dst = g_SWf + (size_t)(l * 2 + c) * WORDS_PER_CHUNK;
        for (int w = tid; w < 2048; w += 256) {
            int g = w >> 5, ln = w & 31;
            uint32_t u[4];
            #pragma unroll
            for (int rg = 0; rg < 4; rg++) {
                int n = ((g >> 2) << 3) | (ln >> 2);
                int j = c * 64 + (((g & 3) << 4) | (rg << 2) | (ln & 3));
                u[rg] = cvt_tf32(SW[j * 128 + n]);
            }
            dst[w] = make_uint4(u[0], u[1], u[2], u[3]);
        }
    }
}

// ---------------------------------------------------------------------------
// Kernel A: per b, for k: C[n][j] = sum_m RW_k[n][m]*H[b][j][m] -> Gf packed
// smem: HB (2 frag buffers) | RC (RW-frag / C-bounce)
// ---------------------------------------------------------------------------
__global__ __launch_bounds__(256, 2) void gemmG_kernel(const float* __restrict__ Hin,
                                                       const uint4* __restrict__ RWf,
                                                       uint4* __restrict__ Gfb)
{
    extern __shared__ char smem[];
    uint32_t sb = smem_u32(smem);
    uint32_t HB = sb;
    uint32_t RC = sb + 2 * FRAG_BYTES;
    float* Cbuf = (float*)(smem + 2 * FRAG_BYTES);

    const int tid = threadIdx.x, wid = tid >> 5, lane = tid & 31;
    const int wy = wid >> 1, wx = wid & 1;
    const int b = blockIdx.x;

    const float4* H4 = (const float4*)(Hin + (size_t)b * 16384);
    uint4* Gout = Gfb + (size_t)b * 8 * WORDS_PER_CHUNK;

    // stage H (B operand) -- both chunks, scatter+cvt
    #pragma unroll
    for (int ch = 0; ch < 2; ch++)
        for (int l = tid; l < 2048; l += 256) {
            int j = l >> 4, q4 = l & 15;
            stageB4(HB + ch * FRAG_BYTES, j, q4 * 4, H4[j * 32 + ch * 16 + q4]);
        }

    for (int k = 0; k < K_; k++) {
        float C[2][8][4];
        #pragma unroll
        for (int m = 0; m < 2; m++)
            #pragma unroll
            for (int t = 0; t < 8; t++)
                #pragma unroll
                for (int r = 0; r < 4; r++) C[m][t][r] = 0.f;

        #pragma unroll
        for (int ch = 0; ch < 2; ch++) {
            __syncthreads();   // RC free
            const uint4* src = RWf + (size_t)(k * 2 + ch) * WORDS_PER_CHUNK;
            for (int l = tid; l < 2048; l += 256)
                cpasync16(RC + (uint32_t)((l >> 5) * 33 + (l & 31)) * 16, src + l);
            CP_COMMIT(); CP_WAIT0();
            __syncthreads();
            uint32_t Bb = HB + ch * FRAG_BYTES;
            #pragma unroll
            for (int p = 0; p < 4; p++) {
                uint32_t bb[8][4];
                #pragma unroll
                for (int t = 0; t < 8; t++)
                    lds128u(bb[t], Bb + (uint32_t)(((((wx * 8 + t) << 2) | p) * 33 + lane)) * 16);
                #pragma unroll
                for (int h = 0; h < 2; h++) {
                    int ks = p * 2 + h;
                    uint32_t aa[2][4];
                    #pragma unroll
                    for (int m = 0; m < 2; m++)
                        lds128u(aa[m], RC + (uint32_t)(((((wy * 2 + m) << 3) | ks) * 33 + lane)) * 16);
                    #pragma unroll
                    for (int m = 0; m < 2; m++)
                        #pragma unroll
                        for (int t = 0; t < 8; t++)
                            mma8(C[m][t], aa[m], bb[t][h * 2], bb[t][h * 2 + 1]);
                }
            }
        }

        // epilogue: bounce halves via smem (cvt'd), write Gf packed
        const int g = lane >> 2, t2 = (lane & 3) * 2;
        #pragma unroll
        for (int hh = 0; hh < 2; hh++) {
            __syncthreads();
            if ((wy >> 1) == hh) {
                #pragma unroll
                for (int m = 0; m < 2; m++) {
                    int nl = (wy & 1) * 32 + m * 16 + g;
                    #pragma unroll
                    for (int t = 0; t < 8; t++) {
                        int j = wx * 64 + t * 8 + t2;
                        sts64u(RC + (uint32_t)(nl * 132 + j) * 4,
                               cvt_tf32(C[m][t][0]), cvt_tf32(C[m][t][1]));
                        sts64u(RC + (uint32_t)((nl + 8) * 132 + j) * 4,
                               cvt_tf32(C[m][t][2]), cvt_tf32(C[m][t][3]));
                    }
                }
            }
            __syncthreads();
            for (int l = tid; l < 2048; l += 256) {
                int nl = l >> 5, j4 = l & 31;
                int n = hh * 64 + nl;
                int kc = j4 >> 2, gq = j4 & 3;
                int gg = ((n >> 3) << 2) | gq;
                int lnn = ((n & 7) << 2) | k;
                uint4 v = *(const uint4*)(Cbuf + nl * 132 + j4 * 4);
                Gout[(size_t)kc * WORDS_PER_CHUNK + gg * 32 + lnn] = v;
            }
        }
    }
}

// ---------------------------------------------------------------------------
// Kernel B: C[i][n] = sum_jk Ef[i][jk]*Gf[n][jk] + sum_j H[i][j]*SW[j][n]
// 10 chunks of K=64 (2 self + 8 msg).  Hot loop = cp.async copies + mma.
// ---------------------------------------------------------------------------
__global__ __launch_bounds__(256, 2) void rgcn_kernel(const float* __restrict__ Hin,
                                                      const uint4* __restrict__ SWf,
                                                      float* __restrict__ Hout)
{
    extern __shared__ char smem[];
    uint32_t sb = smem_u32(smem);
    uint32_t Ab = sb;
    uint32_t Bb = Ab + FRAG_BYTES;

    const int tid = threadIdx.x, wid = tid >> 5, lane = tid & 31;
    const int wy = wid >> 1, wx = wid & 1;
    const int b = blockIdx.x;

    const float4* H4 = (const float4*)(Hin + (size_t)b * 16384);
    const uint4* Efb = g_Ef + (size_t)b * 8 * WORDS_PER_CHUNK;
    const uint4* Gfb = g_Gf + (size_t)b * 8 * WORDS_PER_CHUNK;

    float C[2][8][4];
    #pragma unroll
    for (int m = 0; m < 2; m++)
        #pragma unroll
        for (int t = 0; t < 8; t++)
            #pragma unroll
            for (int r = 0; r < 4; r++) C[m][t][r] = 0.f;

    for (int c = 0; c < 10; c++) {
        if (c < 2) {
            const uint4* sw = SWf + (size_t)c * WORDS_PER_CHUNK;
            for (int l = tid; l < 2048; l += 256)
                cpasync16(Bb + (uint32_t)((l >> 5) * 33 + (l & 31)) * 16, sw + l);
            CP_COMMIT();
            for (int l = tid; l < 2048; l += 256) {
                int i = l >> 4, q4 = l & 15;
                stageA4(Ab, i, q4 * 4, H4[i * 32 + c * 16 + q4]);
            }
            CP_WAIT0();
        } else {
            const uint4* es = Efb + (size_t)(c - 2) * WORDS_PER_CHUNK;
            const uint4* gs = Gfb + (size_t)(c - 2) * WORDS_PER_CHUNK;
            for (int l = tid; l < 2048; l += 256) {
                uint32_t so = (uint32_t)((l >> 5) * 33 + (l & 31)) * 16;
                cpasync16(Ab + so, es + l);
                cpasync16(Bb + so, gs + l);
            }
            CP_COMMIT(); CP_WAIT0();
        }
        __syncthreads();
        #pragma unroll
        for (int p = 0; p < 4; p++) {
            uint32_t bb[8][4];
            #pragma unroll
            for (int t = 0; t < 8; t++)
                lds128u(bb[t], Bb + (uint32_t)(((((wx * 8 + t) << 2) | p) * 33 + lane)) * 16);
            #pragma unroll
            for (int h = 0; h < 2; h++) {
                int ks = p * 2 + h;
                uint32_t aa[2][4];
                #pragma unroll
                for (int m = 0; m < 2; m++)
                    lds128u(aa[m], Ab + (uint32_t)(((((wy * 2 + m) << 3) | ks) * 33 + lane)) * 16);
                #pragma unroll
                for (int m = 0; m < 2; m++)
                    #pragma unroll
                    for (int t = 0; t < 8; t++)
                        mma8(C[m][t], aa[m], bb[t][h * 2], bb[t][h * 2 + 1]);
            }
        }
        __syncthreads();
    }

    // epilogue: sigmoid (D already folded into Ef)
    const int g = lane >> 2, t2 = (lane & 3) * 2;
    float* orow = Hout + (size_t)b * 16384;
    #pragma unroll
    for (int m = 0; m < 2; m++) {
        int i0 = wy * 32 + m * 16 + g;
        #pragma unroll
        for (int t = 0; t < 8; t++) {
            int n0 = wx * 64 + t * 8 + t2;
            orow[i0 * 128 + n0]           = 1.0f / (1.0f + expf(-C[m][t][0]));
            orow[i0 * 128 + n0 + 1]       = 1.0f / (1.0f + expf(-C[m][t][1]));
            orow[(i0 + 8) * 128 + n0]     = 1.0f / (1.0f + expf(-C[m][t][2]));
            orow[(i0 + 8) * 128 + n0 + 1] = 1.0f / (1.0f + expf(-C[m][t][3]));
        }
    }
}

// ---------------------------------------------------------------------------
// MLP head + reduce
// ---------------------------------------------------------------------------
__global__ void mlp_kernel(const float* __restrict__ H3,
                           const float* __restrict__ W1, const float* __restrict__ b1,
                           const float* __restrict__ W2, const float* __restrict__ b2)
{
    __shared__ float W1s[F_ * 20];
    __shared__ float red[128];
    const int b = blockIdx.x;
    const int tid = threadIdx.x;

    for (int l = tid; l < F_ * 20; l += 128) W1s[l] = W1[l];
    __syncthreads();

    const float* hrow = H3 + ((size_t)b * N_ + tid) * F_;
    float h[20];
    #pragma unroll
    for (int o = 0; o < 20; o++) h[o] = b1[o];
    for (int j = 0; j < F_; j++) {
        float hv = hrow[j];
        #pragma unroll
        for (int o = 0; o < 20; o++) h[o] = fmaf(hv, W1s[j * 20 + o], h[o]);
    }
    float z = b2[0];
    #pragma unroll
    for (int o = 0; o < 20; o++) {
        float t = h[o];
        t = fmaxf(t, 0.1f * t);
        z = fmaf(t, W2[o], z);
    }
    red[tid] = 1.0f / (1.0f + expf(-z));
    __syncthreads();
    #pragma unroll
    for (int o = 64; o > 0; o >>= 1) {
        if (tid < o) red[tid] += red[tid + o];
        __syncthreads();
    }
    if (tid == 0) g_part[b] = red[0];
}

__global__ void reduce_kernel(float* __restrict__ out) {
    __shared__ float red[512];
    const int tid = threadIdx.x;
    red[tid] = g_part[tid];
    __syncthreads();
    #pragma unroll
    for (int o = 256; o > 0; o >>= 1) {
        if (tid < o) red[tid] += red[tid + o];
        __syncthreads();
    }
    if (tid == 0) out[0] = red[0] / (float)(B_ * N_);
}

// ---------------------------------------------------------------------------
extern "C" void kernel_launch(void* const* d_in, const int* in_sizes, int n_in,
                              void* d_out, int out_size)
{
    const float* H   = (const float*)d_in[0];
    const float* E   = (const float*)d_in[1];
    const float* RW1 = (const float*)d_in[2];
    const float* SW1 = (const float*)d_in[3];
    const float* RW2 = (const float*)d_in[4];
    const float* SW2 = (const float*)d_in[5];
    const float* RW3 = (const float*)d_in[6];
    const float* SW3 = (const float*)d_in[7];
    const float* W1  = (const float*)d_in[8];
    const float* b1  = (const float*)d_in[9];
    const float* W2  = (const float*)d_in[10];
    const float* b2  = (const float*)d_in[11];

    float *bufA = nullptr, *bufB = nullptr;
    uint4 *RWf = nullptr, *SWf = nullptr, *Gf = nullptr;
    cudaGetSymbolAddress((void**)&bufA, g_bufA);
    cudaGetSymbolAddress((void**)&bufB, g_bufB);
    cudaGetSymbolAddress((void**)&RWf,  g_RWf);
    cudaGetSymbolAddress((void**)&SWf,  g_SWf);
    cudaGetSymbolAddress((void**)&Gf,   g_Gf);

    const int smemA = 3 * FRAG_BYTES;        // 101376
    const int smemB = 2 * FRAG_BYTES;        // 67584
    cudaFuncSetAttribute(gemmG_kernel, cudaFuncAttributeMaxDynamicSharedMemorySize, smemA);
    cudaFuncSetAttribute(rgcn_kernel,  cudaFuncAttributeMaxDynamicSharedMemorySize, smemB);

    deg_kernel<<<(B_ * N_) / 8, 256>>>(E);
    escale_kernel<<<B_, 256>>>(E);
    prep_kernel<<<30, 256>>>(RW1, SW1, RW2, SW2, RW3, SW3);

    gemmG_kernel<<<B_, 256, smemA>>>(H, RWf + 0 * 8 * WORDS_PER_CHUNK, Gf);
    rgcn_kernel<<<B_, 256, smemB>>>(H, SWf + 0 * 2 * WORDS_PER_CHUNK, bufA);

    gemmG_kernel<<<B_, 256, smemA>>>(bufA, RWf + 1 * 8 * WORDS_PER_CHUNK, Gf);
    rgcn_kernel<<<B_, 256, smemB>>>(bufA, SWf + 1 * 2 * WORDS_PER_CHUNK, bufB);

    gemmG_kernel<<<B_, 256, smemA>>>(bufB, RWf + 2 * 8 * WORDS_PER_CHUNK, Gf);
    rgcn_kernel<<<B_, 256, smemB>>>(bufB, SWf + 2 * 2 * WORDS_PER_CHUNK, bufA);

    mlp_kernel<<<B_, 128>>>(bufA, W1, b1, W2, b2);
    reduce_kernel<<<1, 512>>>((float*)d_out);
}

// round 6
// speedup vs baseline: 1.1002x; 1.1002x over previous
#include <cuda_runtime.h>
#include <cstdint>
#include <math.h>

#define B_ 512
#define HWORDS 1024                 // 16B words per half-chunk (128 x 32 tf32)
#define HBYTES 16896                // 32 groups * 33 slots * 16B (padded)
#define RGCN_SMEM  (3 * 2 * HBYTES) // 101376
#define GEMMG_SMEM (6 * HBYTES)     // 101376
#define PACK_SMEM  (128 * 132 * 4)  // 67584

// ---------------- device scratch (allocation-free) ----------------
__device__ float g_H[(size_t)B_ * 16384];           // plain H (layer output)
__device__ float g_D[B_ * 128];
__device__ float g_part[B_];
__device__ uint4 g_Ef[(size_t)B_ * 16 * HWORDS];    // A-frag D*E, 16 halves of jk
__device__ uint4 g_Gf[(size_t)B_ * 16 * HWORDS];    // B-frag G,   16 halves of jk
__device__ uint4 g_HA[(size_t)B_ * 4 * HWORDS];     // A-frag H (self term)
__device__ uint4 g_HB[(size_t)B_ * 4 * HWORDS];     // B-frag H (gemmG operand)
__device__ uint4 g_RWf[3 * 4 * 4 * HWORDS];         // A-frag RW [l][k][mh]
__device__ uint4 g_SWf[3 * 4 * HWORDS];             // B-frag SW [l][ch]

// ---------------- helpers ----------------
__device__ __forceinline__ uint32_t smem_u32(const void* p) {
    uint32_t a;
    asm("{ .reg .u64 t; cvta.to.shared.u64 t, %1; cvt.u32.u64 %0, t; }" : "=r"(a) : "l"(p));
    return a;
}
__device__ __forceinline__ uint32_t cvt_tf32(float x) {
    uint32_t u; asm("cvt.rna.tf32.f32 %0, %1;" : "=r"(u) : "f"(x)); return u;
}
__device__ __forceinline__ void lds128u(uint32_t* r, uint32_t a) {
    asm volatile("ld.shared.v4.b32 {%0,%1,%2,%3}, [%4];"
                 : "=r"(r[0]), "=r"(r[1]), "=r"(r[2]), "=r"(r[3]) : "r"(a));
}
__device__ __forceinline__ void cpasync16(uint32_t sa, const void* ga) {
    asm volatile("cp.async.cg.shared.global [%0], [%1], 16;" :: "r"(sa), "l"(ga));
}
#define CP_COMMIT() asm volatile("cp.async.commit_group;" ::: "memory")
#define CP_WAIT(n)  asm volatile("cp.async.wait_group %0;" :: "n"(n) : "memory")

__device__ __forceinline__ void mma8(float* c, const uint32_t* a, uint32_t b0, uint32_t b1) {
    asm volatile(
        "mma.sync.aligned.m16n8k8.row.col.f32.tf32.tf32.f32 "
        "{%0,%1,%2,%3}, {%4,%5,%6,%7}, {%8,%9}, {%0,%1,%2,%3};"
        : "+f"(c[0]), "+f"(c[1]), "+f"(c[2]), "+f"(c[3])
        : "r"(a[0]), "r"(a[1]), "r"(a[2]), "r"(a[3]), "r"(b0), "r"(b1));
}
__device__ __forceinline__ float sigf(float x) { return 1.0f / (1.0f + expf(-x)); }

// smem slot address for word w (dense gmem order) in padded layout
__device__ __forceinline__ uint32_t wslot(int w) {
    return (uint32_t)((w >> 5) * 33 + (w & 31)) * 16;
}

// half-chunk mma: A at Ab, B at Bb, accumulate into C[2][8][4]
__device__ __forceinline__ void mma_half(uint32_t Ab, uint32_t Bb, int wy, int wx, int lane,
                                         float C[2][8][4]) {
    #pragma unroll
    for (int p = 0; p < 2; p++) {
        uint32_t bb[8][4];
        #pragma unroll
        for (int t = 0; t < 8; t++)
            lds128u(bb[t], Bb + (uint32_t)((((wx * 8 + t) * 2 + p) * 33 + lane)) * 16);
        #pragma unroll
        for (int h = 0; h < 2; h++) {
            int ks = p * 2 + h;
            uint32_t aa[2][4];
            #pragma unroll
            for (int m = 0; m < 2; m++)
                lds128u(aa[m], Ab + (uint32_t)((((wy * 2 + m) * 4 + ks) * 33 + lane)) * 16);
            #pragma unroll
            for (int m = 0; m < 2; m++)
                #pragma unroll
                for (int t = 0; t < 8; t++)
                    mma8(C[m][t], aa[m], bb[t][h * 2], bb[t][h * 2 + 1]);
        }
    }
}

// Emit HA (A-frag) + HB (B-frag) from plain smem P (row stride 132 floats)
__device__ __forceinline__ void emit_packed(const float* P, int b, int tid) {
    uint4* haw = g_HA + (size_t)b * 4 * HWORDS;
    uint4* hbw = g_HB + (size_t)b * 4 * HWORDS;
    for (int w = tid; w < 4096; w += 256) {
        int ch = w >> 10, ww = w & 1023, g = ww >> 5, ln = ww & 31;
        int r0 = (g >> 2) * 16 + (ln >> 2);
        int n0 = ch * 32 + (g & 3) * 8 + (ln & 3);
        uint4 u;
        u.x = cvt_tf32(P[r0 * 132 + n0]);
        u.y = cvt_tf32(P[(r0 + 8) * 132 + n0]);
        u.z = cvt_tf32(P[r0 * 132 + n0 + 4]);
        u.w = cvt_tf32(P[(r0 + 8) * 132 + n0 + 4]);
        haw[w] = u;
    }
    for (int w = tid; w < 4096; w += 256) {
        int mh = w >> 10, ww = w & 1023, g = ww >> 5, ln = ww & 31;
        int c = (g >> 1) * 8 + (ln >> 2);
        int m0 = mh * 32 + (g & 1) * 16 + (ln & 3);
        uint4 u;
        u.x = cvt_tf32(P[c * 132 + m0]);
        u.y = cvt_tf32(P[c * 132 + m0 + 4]);
        u.z = cvt_tf32(P[c * 132 + m0 + 8]);
        u.w = cvt_tf32(P[c * 132 + m0 + 12]);
        hbw[w] = u;
    }
}

// ---------------------------------------------------------------------------
// Degree norm
// ---------------------------------------------------------------------------
__global__ void deg_kernel(const float* __restrict__ E) {
    int warp = (blockIdx.x * blockDim.x + threadIdx.x) >> 5;
    int lane = threadIdx.x & 31;
    if (warp >= B_ * 128) return;
    const float* row = E + (size_t)warp * 512;
    float s = 0.f;
    #pragma unroll 4
    for (int t = lane; t < 512; t += 32) s += row[t];
    #pragma unroll
    for (int o = 16; o > 0; o >>= 1) s += __shfl_xor_sync(0xffffffffu, s, o);
    if (lane == 0) g_D[warp] = 1.0f / (s + 4.0f);
}

// ---------------------------------------------------------------------------
// escale: Ef = A-frag packed tf32(D[i]*E[b][i][jk]), 16 jk-halves per b
// ---------------------------------------------------------------------------
__global__ __launch_bounds__(256) void escale_kernel(const float* __restrict__ E) {
    __shared__ float Dsh[128];
    __shared__ float Es[128 * 36];
    const int b = blockIdx.x, tid = threadIdx.x;
    if (tid < 128) Dsh[tid] = g_D[b * 128 + tid];
    const float4* E4 = (const float4*)(E + (size_t)b * 65536);
    uint4* efb = g_Ef + (size_t)b * 16 * HWORDS;

    for (int kc = 0; kc < 16; kc++) {
        __syncthreads();
        for (int l = tid; l < 1024; l += 256) {
            int i = l >> 3, q = l & 7;
            float4 v = E4[(size_t)i * 128 + kc * 8 + q];
            float d = Dsh[i];
            v.x *= d; v.y *= d; v.z *= d; v.w *= d;
            *(float4*)&Es[i * 36 + q * 4] = v;
        }
        __syncthreads();
        for (int w = tid; w < 1024; w += 256) {
            int g = w >> 5, ln = w & 31;
            int r0 = (g >> 2) * 16 + (ln >> 2);
            int klb = (g & 3) * 8 + (ln & 3);
            uint4 u;
            u.x = cvt_tf32(Es[r0 * 36 + klb]);
            u.y = cvt_tf32(Es[(r0 + 8) * 36 + klb]);
            u.z = cvt_tf32(Es[r0 * 36 + klb + 4]);
            u.w = cvt_tf32(Es[(r0 + 8) * 36 + klb + 4]);
            efb[kc * HWORDS + w] = u;
        }
    }
}

// ---------------------------------------------------------------------------
// prep: RWf A-frag [l][k][mh], SWf B-frag [l][ch]
// ---------------------------------------------------------------------------
__global__ void prep_kernel(const float* __restrict__ RW1, const float* __restrict__ SW1,
                            const float* __restrict__ RW2, const float* __restrict__ SW2,
                            const float* __restrict__ RW3, const float* __restrict__ SW3)
{
    int bid = blockIdx.x, tid = threadIdx.x;
    const float* RWs[3] = {RW1, RW2, RW3};
    const float* SWs[3] = {SW1, SW2, SW3};
    if (bid < 48) {
        int l = bid >> 4, k = (bid >> 2) & 3, mh = bid & 3;
        const float* RW = RWs[l];
        uint4* dst = g_RWf + (size_t)bid * HWORDS;
        for (int w = tid; w < 1024; w += 256) {
            int g = w >> 5, ln = w & 31;
            int r0 = (g >> 2) * 16 + (ln >> 2);
            int m0 = mh * 32 + (g & 3) * 8 + (ln & 3);
            uint4 u;
            u.x = cvt_tf32(RW[((size_t)m0 * 128 + r0) * 4 + k]);
            u.y = cvt_tf32(RW[((size_t)m0 * 128 + r0 + 8) * 4 + k]);
            u.z = cvt_tf32(RW[((size_t)(m0 + 4) * 128 + r0) * 4 + k]);
            u.w = cvt_tf32(RW[((size_t)(m0 + 4) * 128 + r0 + 8) * 4 + k]);
            dst[w] = u;
        }
    } else {
        int sid = bid - 48;
        const float* SW = SWs[sid >> 2];
        int ch = sid & 3;
        uint4* dst = g_SWf + (size_t)sid * HWORDS;
        for (int w = tid; w < 1024; w += 256) {
            int g = w >> 5, ln = w & 31;
            int c = (g >> 1) * 8 + (ln >> 2);
            int j0 = ch * 32 + (g & 1) * 16 + (ln & 3);
            uint4 u;
            u.x = cvt_tf32(SW[(size_t)j0 * 128 + c]);
            u.y = cvt_tf32(SW[(size_t)(j0 + 4) * 128 + c]);
            u.z = cvt_tf32(SW[(size_t)(j0 + 8) * 128 + c]);
            u.w = cvt_tf32(SW[(size_t)(j0 + 12) * 128 + c]);
            dst[w] = u;
        }
    }
}

// ---------------------------------------------------------------------------
// pack0: bootstrap HA/HB from input H
// ---------------------------------------------------------------------------
__global__ __launch_bounds__(256) void pack0_kernel(const float* __restrict__ Hin) {
    extern __shared__ float P[];
    const int b = blockIdx.x, tid = threadIdx.x;
    const float4* H4 = (const float4*)(Hin + (size_t)b * 16384);
    for (int w = tid; w < 4096; w += 256) {
        int i = w >> 5, q = w & 31;
        *(float4*)&P[i * 132 + q * 4] = H4[i * 32 + q];
    }
    __syncthreads();
    emit_packed(P, b, tid);
}

// ---------------------------------------------------------------------------
// gemmG: per b,k: G_k[j][n] = sum_m RW_k[n][m] * H[j][m] -> Gf (B-frag)
// smem: HB resident (4 halves) + RW ring (2)
// ---------------------------------------------------------------------------
__global__ __launch_bounds__(256, 2) void gemmG_kernel(const uint4* __restrict__ RWf) {
    extern __shared__ char smem[];
    uint32_t sb = smem_u32(smem);
    const int tid = threadIdx.x, wid = tid >> 5, lane = tid & 31;
    const int wy = wid >> 1, wx = wid & 1;
    const int b = blockIdx.x;
    const uint4* hb = g_HB + (size_t)b * 4 * HWORDS;
    uint32_t* gfw = (uint32_t*)(g_Gf + (size_t)b * 16 * HWORDS);

    // prologue: group0 = HB(all) + RW stage0; group1 = RW stage1
    #pragma unroll
    for (int hh = 0; hh < 4; hh++)
        for (int w = tid; w < 1024; w += 256)
            cpasync16(sb + hh * HBYTES + wslot(w), hb + hh * HWORDS + w);
    for (int w = tid; w < 1024; w += 256)
        cpasync16(sb + 4 * HBYTES + wslot(w), RWf + w);
    CP_COMMIT();
    for (int w = tid; w < 1024; w += 256)
        cpasync16(sb + 5 * HBYTES + wslot(w), RWf + HWORDS + w);
    CP_COMMIT();

    float C[2][8][4];
    #pragma unroll
    for (int m = 0; m < 2; m++)
        #pragma unroll
        for (int t = 0; t < 8; t++)
            #pragma unroll
            for (int r = 0; r < 4; r++) C[m][t][r] = 0.f;

    const int g4 = lane >> 2, t2 = (lane & 3) * 2;

    for (int s = 0; s < 16; s++) {
        int k = s >> 2, mh = s & 3;
        if (s == 15) CP_WAIT(0); else CP_WAIT(1);
        __syncthreads();
        mma_half(sb + (4 + (s & 1)) * HBYTES, sb + mh * HBYTES, wy, wx, lane, C);
        if (mh == 3) {
            // write Gf for this k directly from registers
            #pragma unroll
            for (int mm = 0; mm < 2; mm++) {
                int n0 = wy * 32 + mm * 16 + g4;
                #pragma unroll
                for (int t = 0; t < 8; t++) {
                    int j0 = wx * 64 + t * 8 + t2;
                    int jh = j0 >> 3;
                    int gj = (j0 & 7) >> 2;
                    uint32_t base0 = (uint32_t)(jh * 1024 + (((n0 >> 3) << 1) | gj) * 32 +
                                                (((n0 & 7) << 2) | k)) * 4 + (j0 & 3);
                    gfw[base0]     = cvt_tf32(C[mm][t][0]);
                    gfw[base0 + 1] = cvt_tf32(C[mm][t][1]);
                    int n1 = n0 + 8;
                    uint32_t base1 = (uint32_t)(jh * 1024 + (((n1 >> 3) << 1) | gj) * 32 +
                                                (((n1 & 7) << 2) | k)) * 4 + (j0 & 3);
                    gfw[base1]     = cvt_tf32(C[mm][t][2]);
                    gfw[base1 + 1] = cvt_tf32(C[mm][t][3]);
                    #pragma unroll
                    for (int r = 0; r < 4; r++) C[mm][t][r] = 0.f;
                }
            }
        }
        __syncthreads();
        if (s + 2 < 16) {
            for (int w = tid; w < 1024; w += 256)
                cpasync16(sb + (4 + (s & 1)) * HBYTES + wslot(w),
                          RWf + (size_t)(s + 2) * HWORDS + w);
            CP_COMMIT();
        }
    }
}

// ---------------------------------------------------------------------------
// rgcn: C[i][n] = sum_jk Ef[i][jk]*Gf[n][jk] + sum_j HA[i][j]*SW[j][n]
// 20 half-chunk stages, 3-deep cp.async ring.  Epilogue: sigmoid -> plain+HA+HB
// ---------------------------------------------------------------------------
__global__ __launch_bounds__(256, 2) void rgcn_kernel(const uint4* __restrict__ SWf) {
    extern __shared__ char smem[];
    uint32_t sb = smem_u32(smem);
    const int tid = threadIdx.x, wid = tid >> 5, lane = tid & 31;
    const int wy = wid >> 1, wx = wid & 1;
    const int b = blockIdx.x;

    const uint4* haw = g_HA + (size_t)b * 4 * HWORDS;
    const uint4* efb = g_Ef + (size_t)b * 16 * HWORDS;
    const uint4* gfb = g_Gf + (size_t)b * 16 * HWORDS;

    auto issue_stage = [&](int s, uint32_t base) {
        const uint4* a = (s < 4) ? (haw + (size_t)s * HWORDS) : (efb + (size_t)(s - 4) * HWORDS);
        const uint4* v = (s < 4) ? (SWf + (size_t)s * HWORDS) : (gfb + (size_t)(s - 4) * HWORDS);
        for (int w = tid; w < 1024; w += 256) {
            uint32_t so = wslot(w);
            cpasync16(base + so, a + w);
            cpasync16(base + HBYTES + so, v + w);
        }
        CP_COMMIT();
    };

    issue_stage(0, sb);
    issue_stage(1, sb + 2 * HBYTES);
    issue_stage(2, sb + 4 * HBYTES);

    float C[2][8][4];
    #pragma unroll
    for (int m = 0; m < 2; m++)
        #pragma unroll
        for (int t = 0; t < 8; t++)
            #pragma unroll
            for (int r = 0; r < 4; r++) C[m][t][r] = 0.f;

    for (int s = 0; s < 20; s++) {
        if (s < 18) CP_WAIT(2);
        else if (s == 18) CP_WAIT(1);
        else CP_WAIT(0);
        __syncthreads();
        uint32_t Ab = sb + (uint32_t)(s % 3) * 2 * HBYTES;
        mma_half(Ab, Ab + HBYTES, wy, wx, lane, C);
        __syncthreads();
        if (s + 3 < 20) issue_stage(s + 3, sb + (uint32_t)(s % 3) * 2 * HBYTES);
    }

    // epilogue: sigmoid -> plain smem bounce -> plain H + HA + HB
    float* P = (float*)smem;
    const int g4 = lane >> 2, t2 = (lane & 3) * 2;
    #pragma unroll
    for (int mm = 0; mm < 2; mm++) {
        int i0 = wy * 32 + mm * 16 + g4;
        #pragma unroll
        for (int t = 0; t < 8; t++) {
            int n0 = wx * 64 + t * 8 + t2;
            P[i0 * 132 + n0]           = sigf(C[mm][t][0]);
            P[i0 * 132 + n0 + 1]       = sigf(C[mm][t][1]);
            P[(i0 + 8) * 132 + n0]     = sigf(C[mm][t][2]);
            P[(i0 + 8) * 132 + n0 + 1] = sigf(C[mm][t][3]);
        }
    }
    __syncthreads();

    float4* ho = (float4*)(g_H + (size_t)b * 16384);
    for (int w = tid; w < 4096; w += 256) {
        int i = w >> 5, q = w & 31;
        ho[i * 32 + q] = *(float4*)&P[i * 132 + q * 4];
    }
    emit_packed(P, b, tid);
}

// ---------------------------------------------------------------------------
// MLP head + reduce
// ---------------------------------------------------------------------------
__global__ void mlp_kernel(const float* __restrict__ W1, const float* __restrict__ b1,
                           const float* __restrict__ W2, const float* __restrict__ b2)
{
    __shared__ float W1s[128 * 20];
    __shared__ float red[128];
    const int b = blockIdx.x;
    const int tid = threadIdx.x;

    for (int l = tid; l < 128 * 20; l += 128) W1s[l] = W1[l];
    __syncthreads();

    const float* hrow = g_H + ((size_t)b * 128 + tid) * 128;
    float h[20];
    #pragma unroll
    for (int o = 0; o < 20; o++) h[o] = b1[o];
    for (int j = 0; j < 128; j++) {
        float hv = hrow[j];
        #pragma unroll
        for (int o = 0; o < 20; o++) h[o] = fmaf(hv, W1s[j * 20 + o], h[o]);
    }
    float z = b2[0];
    #pragma unroll
    for (int o = 0; o < 20; o++) {
        float t = h[o];
        t = fmaxf(t, 0.1f * t);
        z = fmaf(t, W2[o], z);
    }
    red[tid] = sigf(z);
    __syncthreads();
    #pragma unroll
    for (int o = 64; o > 0; o >>= 1) {
        if (tid < o) red[tid] += red[tid + o];
        __syncthreads();
    }
    if (tid == 0) g_part[b] = red[0];
}

__global__ void reduce_kernel(float* __restrict__ out) {
    __shared__ float red[512];
    const int tid = threadIdx.x;
    red[tid] = g_part[tid];
    __syncthreads();
    #pragma unroll
    for (int o = 256; o > 0; o >>= 1) {
        if (tid < o) red[tid] += red[tid + o];
        __syncthreads();
    }
    if (tid == 0) out[0] = red[0] / (float)(B_ * 128);
}

// ---------------------------------------------------------------------------
extern "C" void kernel_launch(void* const* d_in, const int* in_sizes, int n_in,
                              void* d_out, int out_size)
{
    const float* H   = (const float*)d_in[0];
    const float* E   = (const float*)d_in[1];
    const float* RW1 = (const float*)d_in[2];
    const float* SW1 = (const float*)d_in[3];
    const float* RW2 = (const float*)d_in[4];
    const float* SW2 = (const float*)d_in[5];
    const float* RW3 = (const float*)d_in[6];
    const float* SW3 = (const float*)d_in[7];
    const float* W1  = (const float*)d_in[8];
    const float* b1  = (const float*)d_in[9];
    const float* W2  = (const float*)d_in[10];
    const float* b2  = (const float*)d_in[11];

    uint4 *RWf = nullptr, *SWf = nullptr;
    cudaGetSymbolAddress((void**)&RWf, g_RWf);
    cudaGetSymbolAddress((void**)&SWf, g_SWf);

    cudaFuncSetAttribute(gemmG_kernel, cudaFuncAttributeMaxDynamicSharedMemorySize, GEMMG_SMEM);
    cudaFuncSetAttribute(rgcn_kernel,  cudaFuncAttributeMaxDynamicSharedMemorySize, RGCN_SMEM);
    cudaFuncSetAttribute(pack0_kernel, cudaFuncAttributeMaxDynamicSharedMemorySize, PACK_SMEM);

    deg_kernel<<<(B_ * 128) / 8, 256>>>(E);
    escale_kernel<<<B_, 256>>>(E);
    prep_kernel<<<60, 256>>>(RW1, SW1, RW2, SW2, RW3, SW3);
    pack0_kernel<<<B_, 256, PACK_SMEM>>>(H);

    for (int l = 0; l < 3; l++) {
        gemmG_kernel<<<B_, 256, GEMMG_SMEM>>>(RWf + (size_t)l * 16 * HWORDS);
        rgcn_kernel<<<B_, 256, RGCN_SMEM>>>(SWf + (size_t)l * 4 * HWORDS);
    }

    mlp_kernel<<<B_, 128>>>(W1, b1, W2, b2);
    reduce_kernel<<<1, 512>>>((float*)d_out);
}

// round 11
// speedup vs baseline: 1.5927x; 1.4477x over previous
#include <cuda_runtime.h>
#include <cstdint>
#include <math.h>

#define B_ 512
#define PSTR 132                    // plain smem row stride (floats)

// Fragment-packed buffers: a "stage" = 128 x 32 contraction slice = 512 uint4 (8KB bf16)
// A-word (uint4) at (rb,ks,lane): a0..a3 per PTX m16n8k16 A fragment
// B-word (uint4) at (nb,lane): {b0k0,b1k0,b0k1,b1k1}

// ---------------- device scratch (allocation-free) ----------------
__device__ float g_H[(size_t)B_ * 16384];            // plain H (after layer 3)
__device__ float g_part[B_];
__device__ uint4 g_Ef[(size_t)B_ * 16 * 512];        // A-frag D*E, u=k*128+j, 16 stages/b
__device__ uint4 g_HA[(size_t)B_ * 2048];            // A-frag H (self term), 4 stages/b
__device__ uint4 g_HB[(size_t)B_ * 2048];            // B-frag H (G compute), 4 m-stages/b
__device__ uint4 g_RWf[3 * 16 * 512];                // A-frag RW [l][k][mc]
__device__ uint4 g_SWf[3 * 4 * 512];                 // B-frag SW [l][sj]

// ---------------- helpers ----------------
__device__ __forceinline__ uint32_t smem_u32(const void* p) {
    uint32_t a;
    asm("{ .reg .u64 t; cvta.to.shared.u64 t, %1; cvt.u32.u64 %0, t; }" : "=r"(a) : "l"(p));
    return a;
}
__device__ __forceinline__ uint32_t bf2(float lo, float hi) {
    uint32_t r; asm("cvt.rn.bf16x2.f32 %0, %1, %2;" : "=r"(r) : "f"(hi), "f"(lo)); return r;
}
__device__ __forceinline__ void lds128u(uint32_t* r, uint32_t a) {
    asm volatile("ld.shared.v4.b32 {%0,%1,%2,%3}, [%4];"
                 : "=r"(r[0]), "=r"(r[1]), "=r"(r[2]), "=r"(r[3]) : "r"(a));
}
__device__ __forceinline__ void sts32u(uint32_t a, uint32_t v) {
    asm volatile("st.shared.b32 [%0], %1;" :: "r"(a), "r"(v));
}
__device__ __forceinline__ void cpasync16(uint32_t sa, const void* ga) {
    asm volatile("cp.async.cg.shared.global [%0], [%1], 16;" :: "r"(sa), "l"(ga));
}
#define CP_COMMIT() asm volatile("cp.async.commit_group;" ::: "memory")
#define CP_WAIT(n)  asm volatile("cp.async.wait_group %0;" :: "n"(n) : "memory")

__device__ __forceinline__ void mma16(float* c, const uint32_t* a, uint32_t b0, uint32_t b1) {
    asm volatile(
        "mma.sync.aligned.m16n8k16.row.col.f32.bf16.bf16.f32 "
        "{%0,%1,%2,%3}, {%4,%5,%6,%7}, {%8,%9}, {%0,%1,%2,%3};"
        : "+f"(c[0]), "+f"(c[1]), "+f"(c[2]), "+f"(c[3])
        : "r"(a[0]), "r"(a[1]), "r"(a[2]), "r"(a[3]), "r"(b0), "r"(b1));
}
__device__ __forceinline__ float sigf(float x) { return 1.0f / (1.0f + expf(-x)); }

// One K=32 stage: A fragments at Aaddr (8KB), B fragments at Baddr (8KB)
__device__ __forceinline__ void mma_stage(uint32_t Aaddr, uint32_t Baddr,
                                          int wy, int wx, int lane, float C[2][8][4]) {
    uint32_t bw[8][4];
    #pragma unroll
    for (int tb = 0; tb < 8; tb++)
        lds128u(bw[tb], Baddr + (uint32_t)((wx * 8 + tb) * 32 + lane) * 16);
    #pragma unroll
    for (int ks = 0; ks < 2; ks++) {
        uint32_t aw[2][4];
        #pragma unroll
        for (int mm = 0; mm < 2; mm++)
            lds128u(aw[mm], Aaddr + (uint32_t)(((wy * 2 + mm) * 2 + ks) * 32 + lane) * 16);
        #pragma unroll
        for (int mm = 0; mm < 2; mm++)
            #pragma unroll
            for (int tb = 0; tb < 8; tb++)
                mma16(C[mm][tb], aw[mm], bw[tb][2 * ks], bw[tb][2 * ks + 1]);
    }
}

// Emit H (plain smem P, stride PSTR) as A-frag (HA: rows i, contraction j)
__device__ __forceinline__ void emit_HA(const float* P, uint4* dst, int tid) {
    for (int w = tid; w < 2048; w += 256) {
        int st = w >> 9, ww = w & 511;
        int rb = ww >> 6, ks = (ww >> 5) & 1, lane = ww & 31;
        int r = rb * 16 + (lane >> 2);
        int j0 = st * 32 + ks * 16 + 2 * (lane & 3);
        uint4 u;
        u.x = bf2(P[r * PSTR + j0],           P[r * PSTR + j0 + 1]);
        u.y = bf2(P[(r + 8) * PSTR + j0],     P[(r + 8) * PSTR + j0 + 1]);
        u.z = bf2(P[r * PSTR + j0 + 8],       P[r * PSTR + j0 + 9]);
        u.w = bf2(P[(r + 8) * PSTR + j0 + 8], P[(r + 8) * PSTR + j0 + 9]);
        dst[w] = u;
    }
}
// Emit H as B-frag (HB: element (m, col j) = H[j][m])
__device__ __forceinline__ void emit_HB(const float* P, uint4* dst, int tid) {
    for (int w = tid; w < 2048; w += 256) {
        int st = w >> 9, ww = w & 511;
        int nb = ww >> 5, lane = ww & 31;
        int jc = nb * 8 + (lane >> 2);
        int m0 = st * 32 + 2 * (lane & 3);
        uint4 u;
        u.x = bf2(P[jc * PSTR + m0],      P[jc * PSTR + m0 + 1]);
        u.y = bf2(P[jc * PSTR + m0 + 8],  P[jc * PSTR + m0 + 9]);
        u.z = bf2(P[jc * PSTR + m0 + 16], P[jc * PSTR + m0 + 17]);
        u.w = bf2(P[jc * PSTR + m0 + 24], P[jc * PSTR + m0 + 25]);
        dst[w] = u;
    }
}

// ---------------------------------------------------------------------------
// escale: fused degree + pack.  Ef[b] stage s=k*4+jc, A-frag of D[i]*E[b][i][j][k]
// ---------------------------------------------------------------------------
__global__ __launch_bounds__(256) void escale_kernel(const float* __restrict__ E) {
    extern __shared__ float Es[];                 // 128 x PSTR chunk buffer
    __shared__ float Dsh[128];
    const int b = blockIdx.x, tid = threadIdx.x;
    const int wid = tid >> 5, lane = tid & 31;
    const float4* E4 = (const float4*)(E + (size_t)b * 65536);
    uint4* efb = g_Ef + (size_t)b * 16 * 512;

    // pass 1: row sums -> D
    for (int r = wid; r < 128; r += 8) {
        float s = 0.f;
        #pragma unroll
        for (int q = 0; q < 4; q++) {
            float4 v = E4[(size_t)r * 128 + q * 32 + lane];
            s += v.x + v.y + v.z + v.w;
        }
        #pragma unroll
        for (int o = 16; o > 0; o >>= 1) s += __shfl_xor_sync(0xffffffffu, s, o);
        if (lane == 0) Dsh[r] = 1.0f / (s + 4.0f);
    }
    __syncthreads();

    // pass 2: per j-chunk (32 j, all k) -> 4 stages
    for (int jc = 0; jc < 4; jc++) {
        __syncthreads();
        for (int l = tid; l < 4096; l += 256) {
            int r = l >> 5, q4 = l & 31;
            *(float4*)&Es[r * PSTR + q4 * 4] = E4[(size_t)r * 128 + jc * 32 + q4];
        }
        __syncthreads();
        #pragma unroll
        for (int k = 0; k < 4; k++) {
            for (int w = tid; w < 512; w += 256) {
                int rb = w >> 6, ks = (w >> 5) & 1, ln = w & 31;
                int r = rb * 16 + (ln >> 2);
                int jl = ks * 16 + 2 * (ln & 3);
                float d0 = Dsh[r], d1 = Dsh[r + 8];
                const float* e0 = Es + r * PSTR;
                const float* e1 = Es + (r + 8) * PSTR;
                uint4 u;
                u.x = bf2(d0 * e0[jl * 4 + k],       d0 * e0[(jl + 1) * 4 + k]);
                u.y = bf2(d1 * e1[jl * 4 + k],       d1 * e1[(jl + 1) * 4 + k]);
                u.z = bf2(d0 * e0[(jl + 8) * 4 + k], d0 * e0[(jl + 9) * 4 + k]);
                u.w = bf2(d1 * e1[(jl + 8) * 4 + k], d1 * e1[(jl + 9) * 4 + k]);
                efb[(size_t)(k * 4 + jc) * 512 + w] = u;
            }
        }
    }
}

// ---------------------------------------------------------------------------
// prep: RW -> A-frag [l][k][mc]; SW -> B-frag [l][sj]
// ---------------------------------------------------------------------------
__global__ void prep_kernel(const float* __restrict__ RW1, const float* __restrict__ SW1,
                            const float* __restrict__ RW2, const float* __restrict__ SW2,
                            const float* __restrict__ RW3, const float* __restrict__ SW3)
{
    int bid = blockIdx.x, tid = threadIdx.x;
    const float* RWs[3] = {RW1, RW2, RW3};
    const float* SWs[3] = {SW1, SW2, SW3};
    if (bid < 48) {
        int l = bid >> 4, k = (bid >> 2) & 3, mc = bid & 3;
        const float* RW = RWs[l];
        uint4* dst = g_RWf + (size_t)(l * 16 + k * 4 + mc) * 512;
        for (int w = tid; w < 512; w += 256) {
            int rb = w >> 6, ks = (w >> 5) & 1, ln = w & 31;
            int r = rb * 16 + (ln >> 2);
            int m0 = mc * 32 + ks * 16 + 2 * (ln & 3);
            uint4 u;
            u.x = bf2(RW[((size_t)m0 * 128 + r) * 4 + k],       RW[((size_t)(m0 + 1) * 128 + r) * 4 + k]);
            u.y = bf2(RW[((size_t)m0 * 128 + r + 8) * 4 + k],   RW[((size_t)(m0 + 1) * 128 + r + 8) * 4 + k]);
            u.z = bf2(RW[((size_t)(m0 + 8) * 128 + r) * 4 + k], RW[((size_t)(m0 + 9) * 128 + r) * 4 + k]);
            u.w = bf2(RW[((size_t)(m0 + 8) * 128 + r + 8) * 4 + k], RW[((size_t)(m0 + 9) * 128 + r + 8) * 4 + k]);
            dst[w] = u;
        }
    } else {
        int sid = bid - 48;
        int l = sid >> 2, sj = sid & 3;
        const float* SW = SWs[l];
        uint4* dst = g_SWf + (size_t)(l * 4 + sj) * 512;
        for (int w = tid; w < 512; w += 256) {
            int nb = w >> 5, ln = w & 31;
            int n = nb * 8 + (ln >> 2);
            int j0 = sj * 32 + 2 * (ln & 3);
            uint4 u;
            u.x = bf2(SW[(size_t)j0 * 128 + n],        SW[(size_t)(j0 + 1) * 128 + n]);
            u.y = bf2(SW[(size_t)(j0 + 8) * 128 + n],  SW[(size_t)(j0 + 9) * 128 + n]);
            u.z = bf2(SW[(size_t)(j0 + 16) * 128 + n], SW[(size_t)(j0 + 17) * 128 + n]);
            u.w = bf2(SW[(size_t)(j0 + 24) * 128 + n], SW[(size_t)(j0 + 25) * 128 + n]);
            dst[w] = u;
        }
    }
}

// ---------------------------------------------------------------------------
// pack0: bootstrap HA/HB from input H
// ---------------------------------------------------------------------------
__global__ __launch_bounds__(256) void pack0_kernel(const float* __restrict__ Hin) {
    extern __shared__ float P[];
    const int b = blockIdx.x, tid = threadIdx.x;
    const float4* H4 = (const float4*)(Hin + (size_t)b * 16384);
    for (int w = tid; w < 4096; w += 256) {
        int i = w >> 5, q = w & 31;
        *(float4*)&P[i * PSTR + q * 4] = H4[i * 32 + q];
    }
    __syncthreads();
    emit_HA(P, g_HA + (size_t)b * 2048, tid);
    emit_HB(P, g_HB + (size_t)b * 2048, tid);
}

// ---------------------------------------------------------------------------
// Fused layer kernel. smem: HB[4][8KB] | G[16][8KB] | ring[3][16KB]
// Phase1 (t=0..15): G_k = RW_k x HB -> G smem (B-frag).
// Phase2 (t=16..19 self, 20..35 msg): C = HA*SW + Ef*G.  Epilogue: sigmoid.
// ---------------------------------------------------------------------------
#define SM_HB 0
#define SM_G  32768
#define SM_RING 163840
#define LAYER_SMEM 212992

__global__ __launch_bounds__(256) void layer_kernel(const uint4* __restrict__ RWl,
                                                    const uint4* __restrict__ SWl,
                                                    int last)
{
    extern __shared__ char smem[];
    uint32_t sb = smem_u32(smem);
    const int tid = threadIdx.x, wid = tid >> 5, lane = tid & 31;
    const int wy = wid >> 1, wx = wid & 1;
    const int b = blockIdx.x;

    const uint4* haw = g_HA + (size_t)b * 2048;
    const uint4* hbw = g_HB + (size_t)b * 2048;
    const uint4* efw = g_Ef + (size_t)b * 16 * 512;

    auto issue = [&](int t) {
        uint32_t base = sb + SM_RING + (uint32_t)(t % 3) * 16384;
        if (t < 16) {
            const uint4* src = RWl + (size_t)t * 512;
            for (int w = tid; w < 512; w += 256) cpasync16(base + w * 16, src + w);
        } else if (t < 20) {
            int s = t - 16;
            const uint4* a = haw + (size_t)s * 512;
            const uint4* v = SWl + (size_t)s * 512;
            for (int w = tid; w < 512; w += 256) {
                cpasync16(base + w * 16, a + w);
                cpasync16(base + 8192 + w * 16, v + w);
            }
        } else {
            const uint4* a = efw + (size_t)(t - 20) * 512;
            for (int w = tid; w < 512; w += 256) cpasync16(base + w * 16, a + w);
        }
        CP_COMMIT();
    };

    // prologue: HB resident copy rides in group 0 with stage 0
    for (int w = tid; w < 2048; w += 256)
        cpasync16(sb + SM_HB + w * 16, hbw + w);
    issue(0); issue(1); issue(2);

    float C[2][8][4];
    #pragma unroll
    for (int mm = 0; mm < 2; mm++)
        #pragma unroll
        for (int tb = 0; tb < 8; tb++)
            #pragma unroll
            for (int r = 0; r < 4; r++) C[mm][tb][r] = 0.f;

    for (int t = 0; t < 36; t++) {
        if (t < 34) CP_WAIT(2);
        else if (t == 34) CP_WAIT(1);
        else CP_WAIT(0);
        __syncthreads();
        uint32_t Aaddr = sb + SM_RING + (uint32_t)(t % 3) * 16384;
        if (t < 16) {
            mma_stage(Aaddr, sb + SM_HB + (uint32_t)(t & 3) * 8192, wy, wx, lane, C);
            if ((t & 3) == 3) {
                int k = t >> 2;
                // G_k epilogue: C[n][j] -> G smem B-frag words, then zero C
                #pragma unroll
                for (int mm = 0; mm < 2; mm++) {
                    int nb0 = wy * 4 + mm * 2;
                    #pragma unroll
                    for (int tb = 0; tb < 8; tb++) {
                        int j0 = wx * 64 + tb * 8 + 2 * (lane & 3);
                        uint32_t seg = (uint32_t)(k * 4 + (j0 >> 5));
                        uint32_t reg = (uint32_t)(2 * ((j0 & 31) >> 4) + (tb & 1));
                        uint32_t base = sb + SM_G + seg * 8192 + reg * 4;
                        sts32u(base + (uint32_t)(nb0 * 32 + lane) * 16,
                               bf2(C[mm][tb][0], C[mm][tb][1]));
                        sts32u(base + (uint32_t)((nb0 + 1) * 32 + lane) * 16,
                               bf2(C[mm][tb][2], C[mm][tb][3]));
                        #pragma unroll
                        for (int r = 0; r < 4; r++) C[mm][tb][r] = 0.f;
                    }
                }
            }
        } else if (t < 20) {
            mma_stage(Aaddr, Aaddr + 8192, wy, wx, lane, C);
        } else {
            mma_stage(Aaddr, sb + SM_G + (uint32_t)(t - 20) * 8192, wy, wx, lane, C);
        }
        __syncthreads();
        if (t + 3 < 36) issue(t + 3);
    }

    // epilogue: sigmoid -> plain P (in G region), then emit packed / plain
    float* P = (float*)(smem + SM_G);
    const int g4 = lane >> 2, t2 = (lane & 3) * 2;
    #pragma unroll
    for (int mm = 0; mm < 2; mm++) {
        int i0 = wy * 32 + mm * 16 + g4;
        #pragma unroll
        for (int tb = 0; tb < 8; tb++) {
            int n0 = wx * 64 + tb * 8 + t2;
            P[i0 * PSTR + n0]           = sigf(C[mm][tb][0]);
            P[i0 * PSTR + n0 + 1]       = sigf(C[mm][tb][1]);
            P[(i0 + 8) * PSTR + n0]     = sigf(C[mm][tb][2]);
            P[(i0 + 8) * PSTR + n0 + 1] = sigf(C[mm][tb][3]);
        }
    }
    __syncthreads();

    if (last) {
        float4* ho = (float4*)(g_H + (size_t)b * 16384);
        for (int w = tid; w < 4096; w += 256) {
            int i = w >> 5, q = w & 31;
            ho[i * 32 + q] = *(float4*)&P[i * PSTR + q * 4];
        }
    } else {
        emit_HA(P, g_HA + (size_t)b * 2048, tid);
        emit_HB(P, g_HB + (size_t)b * 2048, tid);
    }
}

// ---------------------------------------------------------------------------
// MLP head + reduce
// ---------------------------------------------------------------------------
__global__ void mlp_kernel(const float* __restrict__ W1, const float* __restrict__ b1,
                           const float* __restrict__ W2, const float* __restrict__ b2)
{
    __shared__ float W1s[128 * 20];
    __shared__ float red[128];
    const int b = blockIdx.x;
    const int tid = threadIdx.x;

    for (int l = tid; l < 128 * 20; l += 128) W1s[l] = W1[l];
    __syncthreads();

    const float* hrow = g_H + ((size_t)b * 128 + tid) * 128;
    float h[20];
    #pragma unroll
    for (int o = 0; o < 20; o++) h[o] = b1[o];
    for (int j = 0; j < 128; j++) {
        float hv = hrow[j];
        #pragma unroll
        for (int o = 0; o < 20; o++) h[o] = fmaf(hv, W1s[j * 20 + o], h[o]);
    }
    float z = b2[0];
    #pragma unroll
    for (int o = 0; o < 20; o++) {
        float t = h[o];
        t = fmaxf(t, 0.1f * t);
        z = fmaf(t, W2[o], z);
    }
    red[tid] = sigf(z);
    __syncthreads();
    #pragma unroll
    for (int o = 64; o > 0; o >>= 1) {
        if (tid < o) red[tid] += red[tid + o];
        __syncthreads();
    }
    if (tid == 0) g_part[b] = red[0];
}

__global__ void reduce_kernel(float* __restrict__ out) {
    __shared__ float red[512];
    const int tid = threadIdx.x;
    red[tid] = g_part[tid];
    __syncthreads();
    #pragma unroll
    for (int o = 256; o > 0; o >>= 1) {
        if (tid < o) red[tid] += red[tid + o];
        __syncthreads();
    }
    if (tid == 0) out[0] = red[0] / (float)(B_ * 128);
}

// ---------------------------------------------------------------------------
extern "C" void kernel_launch(void* const* d_in, const int* in_sizes, int n_in,
                              void* d_out, int out_size)
{
    const float* H   = (const float*)d_in[0];
    const float* E   = (const float*)d_in[1];
    const float* RW1 = (const float*)d_in[2];
    const float* SW1 = (const float*)d_in[3];
    const float* RW2 = (const float*)d_in[4];
    const float* SW2 = (const float*)d_in[5];
    const float* RW3 = (const float*)d_in[6];
    const float* SW3 = (const float*)d_in[7];
    const float* W1  = (const float*)d_in[8];
    const float* b1  = (const float*)d_in[9];
    const float* W2  = (const float*)d_in[10];
    const float* b2  = (const float*)d_in[11];

    uint4 *RWf = nullptr, *SWf = nullptr;
    cudaGetSymbolAddress((void**)&RWf, g_RWf);
    cudaGetSymbolAddress((void**)&SWf, g_SWf);

    const int ES_SMEM = 128 * PSTR * 4;     // 67584
    cudaFuncSetAttribute(escale_kernel, cudaFuncAttributeMaxDynamicSharedMemorySize, ES_SMEM);
    cudaFuncSetAttribute(pack0_kernel,  cudaFuncAttributeMaxDynamicSharedMemorySize, ES_SMEM);
    cudaFuncSetAttribute(layer_kernel,  cudaFuncAttributeMaxDynamicSharedMemorySize, LAYER_SMEM);

    prep_kernel<<<60, 256>>>(RW1, SW1, RW2, SW2, RW3, SW3);
    escale_kernel<<<B_, 256, ES_SMEM>>>(E);
    pack0_kernel<<<B_, 256, ES_SMEM>>>(H);

    for (int l = 0; l < 3; l++)
        layer_kernel<<<B_, 256, LAYER_SMEM>>>(RWf + (size_t)l * 16 * 512,
                                              SWf + (size_t)l * 4 * 512,
                                              l == 2);

    mlp_kernel<<<B_, 128>>>(W1, b1, W2, b2);
    reduce_kernel<<<1, 512>>>((float*)d_out);
}